// round 17
// baseline (speedup 1.0000x reference)
#include <cuda_runtime.h>
#include <math.h>

#define B_   2
#define T_   2048
#define S_   2048
#define E_   1024
#define H_   16
#define DH_  64
#define SCALE_ 0.125f
#define CLAMP_V 50000.0f

// Scratch (device globals: no allocations allowed)
__device__ float  g_Qp[B_ * T_ * E_];
__device__ float  g_Kp[B_ * S_ * E_];
__device__ float  g_Vp[B_ * S_ * E_];
__device__ float  g_ctx[B_ * T_ * E_];

// ---------------------------------------------------------------------------
__device__ __forceinline__ unsigned smem_u32(const void* p) {
    unsigned r;
    asm("{ .reg .u64 t; cvta.to.shared.u64 t, %1; cvt.u32.u64 %0, t; }"
        : "=r"(r) : "l"(p));
    return r;
}

// bulk copy global -> shared::cta, completion via mbarrier complete_tx
#define BULKCP(dst, src, sz, mb)                                           \
    asm volatile(                                                          \
        "cp.async.bulk.shared::cta.global.mbarrier::complete_tx::bytes "   \
        "[%0], [%1], %2, [%3];"                                            \
        :: "r"(dst), "l"(src), "r"(sz), "r"(mb) : "memory")

#define MBAR_INIT(mb, cnt) \
    asm volatile("mbarrier.init.shared.b64 [%0], %1;" :: "r"(mb), "r"(cnt) : "memory")

#define MBAR_EXPECT(mb, bytes) \
    asm volatile("mbarrier.arrive.expect_tx.shared.b64 _, [%0], %1;" \
                 :: "r"(mb), "r"(bytes) : "memory")

#define MBAR_WAITP(mb, parity) do {                                        \
    unsigned _mb = (mb), _ph = (parity), _done;                            \
    asm volatile(                                                          \
        "{\n\t.reg .pred p;\n\t"                                           \
        "mbarrier.try_wait.parity.acquire.cta.shared::cta.b64 p, [%1], %2;\n\t" \
        "selp.b32 %0, 1, 0, p;\n\t}"                                       \
        : "=r"(_done) : "r"(_mb), "r"(_ph) : "memory");                    \
    if (!_done) {                                                          \
        asm volatile(                                                      \
            "{\n\t.reg .pred P1;\n\t"                                      \
            "W_LOOP_%=:\n\t"                                               \
            "mbarrier.try_wait.parity.acquire.cta.shared::cta.b64 P1, [%0], %1, 0x989680;\n\t" \
            "@P1 bra.uni W_DONE_%=;\n\t"                                   \
            "bra.uni W_LOOP_%=;\n\t"                                       \
            "W_DONE_%=:\n\t}"                                              \
            :: "r"(_mb), "r"(_ph) : "memory");                             \
    }                                                                      \
} while (0)

__device__ __forceinline__ unsigned cvt_tf32(float x) {
    unsigned r;
    asm("cvt.rna.tf32.f32 %0, %1;" : "=r"(r) : "f"(x));
    return r;
}
__device__ __forceinline__ float tf32f(float x) {
    return __uint_as_float(cvt_tf32(x));
}

__device__ __forceinline__ void mma8(float* d, const unsigned* a, const unsigned* b) {
    asm volatile(
        "mma.sync.aligned.m16n8k8.row.col.f32.tf32.tf32.f32 "
        "{%0,%1,%2,%3}, {%4,%5,%6,%7}, {%8,%9}, {%0,%1,%2,%3};"
        : "+f"(d[0]), "+f"(d[1]), "+f"(d[2]), "+f"(d[3])
        : "r"(a[0]), "r"(a[1]), "r"(a[2]), "r"(a[3]), "r"(b[0]), "r"(b[1]));
}

__device__ __forceinline__ void softmax_merge(float& m, float& s, float om, float os) {
    float nm = fmaxf(m, om);
    if (nm == -INFINITY) { m = nm; s = 0.f; return; }
    s = s * __expf(m - nm) + os * __expf(om - nm);
    m = nm;
}

// Fragment compute from RAW row-major smem (pad 20), cvt at load. 64x32 warp tile.
#define K8_RAW(As_, Bs_, kk, mbase, nbase, acc)                            \
    do {                                                                   \
        unsigned af[4][4], bf[4][2];                                       \
        _Pragma("unroll")                                                  \
        for (int i = 0; i < 4; i++) {                                      \
            int mr = (mbase) + i * 16 + lr;                                \
            af[i][0] = cvt_tf32((As_)[mr][(kk) + lc]);                     \
            af[i][1] = cvt_tf32((As_)[mr + 8][(kk) + lc]);                 \
            af[i][2] = cvt_tf32((As_)[mr][(kk) + 4 + lc]);                 \
            af[i][3] = cvt_tf32((As_)[mr + 8][(kk) + 4 + lc]);             \
        }                                                                  \
        _Pragma("unroll")                                                  \
        for (int j = 0; j < 4; j++) {                                      \
            int nr = (nbase) + j * 8 + lr;                                 \
            bf[j][0] = cvt_tf32((Bs_)[nr][(kk) + lc]);                     \
            bf[j][1] = cvt_tf32((Bs_)[nr][(kk) + 4 + lc]);                 \
        }                                                                  \
        _Pragma("unroll")                                                  \
        for (int i = 0; i < 4; i++)                                        \
            _Pragma("unroll")                                              \
            for (int j = 0; j < 4; j++)                                    \
                mma8(acc[i][j], af[i], bf[j]);                             \
    } while (0)

struct GemmArgs {
    const float* A[3];
    const float* W[3];
    const float* bias[3];
    float*       C[3];
    float        alpha[3];
};

// ---------------------------------------------------------------------------
// NT GEMM + bias + alpha.  BM=BN=128, BK=16, 256 thr, 8 warps (2m x 4n),
// warp tile 64x32.  cp.async.bulk (1 row per thread) + mbarrier, 2 buffers.
// ---------------------------------------------------------------------------
__global__ __launch_bounds__(256) void gemm_nt_bias(
    GemmArgs ga, int K, int lda, int ldb, int ldc)
{
    const int z = blockIdx.z;
    const float* A    = ga.A[z];
    const float* Bm   = ga.W[z];
    const float* bias = ga.bias[z];
    float*       C    = ga.C[z];
    const float  alpha = ga.alpha[z];

    __shared__ float As[2][128][20];
    __shared__ float Bs[2][128][20];
    __shared__ __align__(8) unsigned long long mbar[2];

    const int tid = threadIdx.x;
    const int lane = tid & 31, w = tid >> 5;
    const int wm = w & 1, wn = w >> 1;
    const int lr = lane >> 2, lc = lane & 3;
    const int bm = blockIdx.y * 128, bn = blockIdx.x * 128;

    // producer role: tid<128 -> A row (tid), else B row (tid-128)
    const int prow = tid & 127;
    const int side = tid >> 7;
    const float* srcRow = side ? (Bm + (size_t)(bn + prow) * ldb)
                               : (A  + (size_t)(bm + prow) * lda);
    const unsigned dstRow = side ? smem_u32(&Bs[0][prow][0])
                                 : smem_u32(&As[0][prow][0]);
    const unsigned mbb = smem_u32(&mbar[0]);
    const unsigned bufStride = 128u * 20u * 4u;

    if (tid == 0) { MBAR_INIT(mbb, 256); MBAR_INIT(mbb + 8, 256); }
    __syncthreads();

#define G_STAGE(kc, buf)                                                   \
    do {                                                                   \
        unsigned mb_ = mbb + (buf) * 8;                                    \
        MBAR_EXPECT(mb_, 64u);                                             \
        BULKCP(dstRow + (unsigned)(buf) * bufStride,                       \
               srcRow + (kc) * 16, 64u, mb_);                              \
    } while (0)

    float acc[4][4][4] = {};

    const int NC = K >> 4;
    G_STAGE(0, 0);
    G_STAGE(1, 1);

    for (int kc = 0; kc < NC; kc++) {
        const int buf = kc & 1;
        MBAR_WAITP(mbb + buf * 8, (kc >> 1) & 1);
        K8_RAW(As[buf], Bs[buf], 0, wm * 64, wn * 32, acc);
        K8_RAW(As[buf], Bs[buf], 8, wm * 64, wn * 32, acc);
        __syncthreads();
        if (kc + 2 < NC) G_STAGE(kc + 2, buf);
    }
#undef G_STAGE

#pragma unroll
    for (int j = 0; j < 4; j++) {
        int col = bn + wn * 32 + j * 8 + lc * 2;
        float b0v = bias[col], b1v = bias[col + 1];
#pragma unroll
        for (int i = 0; i < 4; i++) {
            int r0 = bm + wm * 64 + i * 16 + lr;
            *(float2*)(C + (size_t)r0 * ldc + col) =
                make_float2(alpha * (acc[i][j][0] + b0v), alpha * (acc[i][j][1] + b1v));
            *(float2*)(C + (size_t)(r0 + 8) * ldc + col) =
                make_float2(alpha * (acc[i][j][2] + b0v), alpha * (acc[i][j][3] + b1v));
        }
    }
}

// ---------------------------------------------------------------------------
// Fused attention (R16 compute, bulk-copy staging):
// Phase 0: online stats over recomputed scores (registers).
// Phase 1: recompute scores, p = exp(clamp(v)-m)*inv (mask->0), write p once,
//          Ps smem bounce, Ctx += P @ V.
// Layout (floats): Q[128][68] | Ps[64][136] | K[64][68] | V[64][72] |
//                  st float2[128] | mk char[2048]
// ---------------------------------------------------------------------------
#define FZ_Q  0
#define FZ_P  8704
#define FZ_K  17408
#define FZ_V  21760
#define FZ_ST 26368
#define FZ_MK 26624
#define FZ_TOT 27136

__global__ __launch_bounds__(256, 2) void attn_fused(
    const float* __restrict__ Qp, const float* __restrict__ Kp,
    const float* __restrict__ Vp, const int* __restrict__ mask,
    float* __restrict__ P, float* __restrict__ Ctx)
{
    extern __shared__ float sm[];
    __shared__ __align__(8) unsigned long long fmbar[5];  // q, k0, k1, k2(p1), v(p1)

    const int bh = blockIdx.y, b = bh >> 4, h = bh & 15;
    const int tid = threadIdx.x;
    const int lane = tid & 31, w = tid >> 5;
    const int wm = w & 1, wn = w >> 1;
    const int lr = lane >> 2, lc = lane & 3;
    const int bm = blockIdx.x * 128;
    const unsigned smb = smem_u32(sm);
    const unsigned mbb = smem_u32(&fmbar[0]);
    const unsigned mbq = mbb, mbk0 = mbb + 8, mbk1 = mbb + 16;
    const unsigned mbk2 = mbb + 24, mbv = mbb + 32;

    if (tid == 0) {
        MBAR_INIT(mbq, 128);
        MBAR_INIT(mbk0, 64); MBAR_INIT(mbk1, 64);
        MBAR_INIT(mbk2, 64); MBAR_INIT(mbv, 64);
    }
    // mask bytes for all S
    {
        char* mk = (char*)(sm + FZ_MK);
        const int* mg = mask + (size_t)b * S_;
#pragma unroll
        for (int u = 0; u < 8; u++) {
            int i = u * 256 + tid;
            mk[i] = (mg[i] != 0);
        }
    }
    __syncthreads();   // barriers inited + mask visible before any arrive/read

    const float* Kg = Kp + (size_t)b * S_ * E_ + h * DH_;
    const float* Vg = Vp + (size_t)b * S_ * E_ + h * DH_;

    // stage Q: 128 rows x 256B, threads 0-127 one bulk each
    {
        const float* Qg = Qp + (size_t)b * T_ * E_ + (size_t)bm * E_ + h * DH_;
        if (tid < 128) {
            MBAR_EXPECT(mbq, 256u);
            BULKCP(smb + (FZ_Q + tid * 68) * 4, Qg + (size_t)tid * E_, 256u, mbq);
        }
    }

#define STAGE_KB(cb, off, str, mb)                                         \
    do { if (tid < 64) {                                                   \
        MBAR_EXPECT(mb, 256u);                                             \
        BULKCP(smb + ((off) + tid * (str)) * 4,                            \
               Kg + (size_t)((cb) * 64 + tid) * E_, 256u, mb);             \
    } } while (0)

#define STAGE_V(cb, mb)                                                    \
    do { if (tid >= 64 && tid < 128) { int r_ = tid - 64;                  \
        MBAR_EXPECT(mb, 256u);                                             \
        BULKCP(smb + (FZ_V + r_ * 72) * 4,                                 \
               Vg + (size_t)((cb) * 64 + r_) * E_, 256u, mb);              \
    } } while (0)

    const char* mk = (const char*)(sm + FZ_MK);
    const float* Qb = sm + FZ_Q;

#define SCORE_MMA(Kb_, kstr_, accs)                                        \
    do {                                                                   \
        _Pragma("unroll")                                                  \
        for (int kt = 0; kt < 8; kt++) {                                   \
            const int kk = kt * 8;                                         \
            unsigned af[4][4], bf[2][2];                                   \
            _Pragma("unroll")                                              \
            for (int i = 0; i < 4; i++) {                                  \
                int mr = wm * 64 + i * 16 + lr;                            \
                af[i][0] = cvt_tf32(Qb[mr * 68 + kk + lc]);                \
                af[i][1] = cvt_tf32(Qb[(mr + 8) * 68 + kk + lc]);          \
                af[i][2] = cvt_tf32(Qb[mr * 68 + kk + 4 + lc]);            \
                af[i][3] = cvt_tf32(Qb[(mr + 8) * 68 + kk + 4 + lc]);      \
            }                                                              \
            _Pragma("unroll")                                              \
            for (int j = 0; j < 2; j++) {                                  \
                int nb = wn * 16 + j * 8 + lr;                             \
                bf[j][0] = cvt_tf32((Kb_)[nb * (kstr_) + kk + lc]);        \
                bf[j][1] = cvt_tf32((Kb_)[nb * (kstr_) + kk + 4 + lc]);    \
            }                                                              \
            _Pragma("unroll")                                              \
            for (int i = 0; i < 4; i++)                                    \
                _Pragma("unroll")                                          \
                for (int j = 0; j < 2; j++)                                \
                    mma8(accs[i][j], af[i], bf[j]);                        \
        }                                                                  \
    } while (0)

    // ------------------ Phase 0: stats (online, registers) ------------------
    STAGE_KB(0, FZ_K, 68, mbk0);
    STAGE_KB(1, FZ_V, 72, mbk1);
    MBAR_WAITP(mbq, 0);

    float m_run[4][2], s_run[4][2];
#pragma unroll
    for (int i = 0; i < 4; i++) {
        m_run[i][0] = -INFINITY; m_run[i][1] = -INFINITY;
        s_run[i][0] = 0.f;       s_run[i][1] = 0.f;
    }

    for (int cb = 0; cb < 32; cb++) {
        const int kb = cb & 1;
        MBAR_WAITP(kb ? mbk1 : mbk0, (cb >> 1) & 1);
        const float* Kb = sm + (kb ? FZ_V : FZ_K);
        const int kstr  = kb ? 72 : 68;

        float acc_s[4][2][4] = {};
        SCORE_MMA(Kb, kstr, acc_s);

#pragma unroll
        for (int i = 0; i < 4; i++) {
#pragma unroll
            for (int hh = 0; hh < 2; hh++) {
                int lcol0 = wn * 16 + lc * 2;
                int g0 = cb * 64 + lcol0, g1 = cb * 64 + lcol0 + 8;
                bool k0 = mk[g0] != 0, k1 = mk[g0 + 1] != 0;
                bool k2 = mk[g1] != 0, k3 = mk[g1 + 1] != 0;
                float v0 = k0 ? fminf(fmaxf(acc_s[i][0][hh * 2],     -CLAMP_V), CLAMP_V) : -INFINITY;
                float v1 = k1 ? fminf(fmaxf(acc_s[i][0][hh * 2 + 1], -CLAMP_V), CLAMP_V) : -INFINITY;
                float v2 = k2 ? fminf(fmaxf(acc_s[i][1][hh * 2],     -CLAMP_V), CLAMP_V) : -INFINITY;
                float v3 = k3 ? fminf(fmaxf(acc_s[i][1][hh * 2 + 1], -CLAMP_V), CLAMP_V) : -INFINITY;
                float bmax = fmaxf(fmaxf(v0, v1), fmaxf(v2, v3));
                if (bmax != -INFINITY) {
                    float nm = fmaxf(m_run[i][hh], bmax);
                    float sc = (m_run[i][hh] == -INFINITY) ? 0.f
                               : s_run[i][hh] * __expf(m_run[i][hh] - nm);
                    s_run[i][hh] = sc + __expf(v0 - nm) + __expf(v1 - nm)
                                      + __expf(v2 - nm) + __expf(v3 - nm);
                    m_run[i][hh] = nm;
                }
            }
        }
        __syncthreads();
        if (cb + 2 < 32) {
            if (kb) STAGE_KB(cb + 2, FZ_V, 72, mbk1);
            else    STAGE_KB(cb + 2, FZ_K, 68, mbk0);
        }
    }

    // merge across lc lanes (shfl), then across wn warps (smem = Ps region)
    {
        float* red_m = sm + FZ_P;          // [4][128]
        float* red_s = sm + FZ_P + 512;    // [4][128]
#pragma unroll
        for (int i = 0; i < 4; i++) {
#pragma unroll
            for (int hh = 0; hh < 2; hh++) {
                float m = m_run[i][hh], s = s_run[i][hh];
#pragma unroll
                for (int off = 1; off <= 2; off <<= 1) {
                    softmax_merge(m, s, __shfl_xor_sync(0xffffffffu, m, off),
                                        __shfl_xor_sync(0xffffffffu, s, off));
                }
                if (lc == 0) {
                    int rl = wm * 64 + i * 16 + lr + hh * 8;
                    red_m[wn * 128 + rl] = m;
                    red_s[wn * 128 + rl] = s;
                }
            }
        }
        __syncthreads();
        if (tid < 128) {
            float m = red_m[tid], s = red_s[tid];
            softmax_merge(m, s, red_m[128 + tid], red_s[128 + tid]);
            softmax_merge(m, s, red_m[256 + tid], red_s[256 + tid]);
            softmax_merge(m, s, red_m[384 + tid], red_s[384 + tid]);
            ((float2*)(sm + FZ_ST))[tid] = make_float2(m, 1.f / s);
        }
        __syncthreads();
    }

    // ------------------ Phase 1: p-write + PV --------------------
    STAGE_KB(0, FZ_K, 68, mbk2);
    STAGE_V(0, mbv);

    float* Pg = P + (size_t)bh * T_ * S_;
    const float2* st = (const float2*)(sm + FZ_ST);

    float acc_c[4][2][4] = {};

    for (int cb = 0; cb < 32; cb++) {
        MBAR_WAITP(mbk2, cb & 1);

        float acc_s[4][2][4] = {};
        SCORE_MMA(sm + FZ_K, 68, acc_s);

        // epilogue: p = exp(clamp(v)-m)*inv (mask->0); write attn + Ps smem
        {
            float* Pb = sm + FZ_P;
#pragma unroll
            for (int i = 0; i < 4; i++) {
                int rl = wm * 64 + i * 16 + lr;
                float2 s0 = st[rl], s1 = st[rl + 8];
                float m0 = (s0.x == -INFINITY) ? 0.f : s0.x;
                float m1 = (s1.x == -INFINITY) ? 0.f : s1.x;
#pragma unroll
                for (int j = 0; j < 2; j++) {
                    int lcol = wn * 16 + j * 8 + lc * 2;
                    int gcol = cb * 64 + lcol;
                    bool k0 = mk[gcol] != 0, k1 = mk[gcol + 1] != 0;
                    float v00 = fminf(fmaxf(acc_s[i][j][0], -CLAMP_V), CLAMP_V);
                    float v01 = fminf(fmaxf(acc_s[i][j][1], -CLAMP_V), CLAMP_V);
                    float v10 = fminf(fmaxf(acc_s[i][j][2], -CLAMP_V), CLAMP_V);
                    float v11 = fminf(fmaxf(acc_s[i][j][3], -CLAMP_V), CLAMP_V);
                    float p00 = k0 ? __expf(v00 - m0) * s0.y : 0.f;
                    float p01 = k1 ? __expf(v01 - m0) * s0.y : 0.f;
                    float p10 = k0 ? __expf(v10 - m1) * s1.y : 0.f;
                    float p11 = k1 ? __expf(v11 - m1) * s1.y : 0.f;
                    *(float2*)(Pg + (size_t)(bm + rl) * S_ + gcol)     = make_float2(p00, p01);
                    *(float2*)(Pg + (size_t)(bm + rl + 8) * S_ + gcol) = make_float2(p10, p11);
                    Pb[lcol * 136 + rl]           = tf32f(p00);
                    Pb[(lcol + 1) * 136 + rl]     = tf32f(p01);
                    Pb[lcol * 136 + rl + 8]       = tf32f(p10);
                    Pb[(lcol + 1) * 136 + rl + 8] = tf32f(p11);
                }
            }
        }
        __syncthreads();   // Ps ready; K region dead

        if (cb + 1 < 32) STAGE_KB(cb + 1, FZ_K, 68, mbk2);

        MBAR_WAITP(mbv, cb & 1);

        // PV: Ctx += P(128x64) @ V(64x64)
        {
            const float* Pb = sm + FZ_P;
            const float* Vb = sm + FZ_V;
#pragma unroll
            for (int kt8 = 0; kt8 < 8; kt8++) {
                const int kk = kt8 * 8;
                unsigned af[4][4], bf[2][2];
#pragma unroll
                for (int i = 0; i < 4; i++) {
                    int mb = wm * 64 + i * 16 + lr;
                    af[i][0] = __float_as_uint(Pb[(kk + lc) * 136 + mb]);
                    af[i][1] = __float_as_uint(Pb[(kk + lc) * 136 + mb + 8]);
                    af[i][2] = __float_as_uint(Pb[(kk + 4 + lc) * 136 + mb]);
                    af[i][3] = __float_as_uint(Pb[(kk + 4 + lc) * 136 + mb + 8]);
                }
#pragma unroll
                for (int j = 0; j < 2; j++) {
                    int nb = wn * 16 + j * 8 + lr;
                    bf[j][0] = cvt_tf32(Vb[(kk + lc) * 72 + nb]);
                    bf[j][1] = cvt_tf32(Vb[(kk + 4 + lc) * 72 + nb]);
                }
#pragma unroll
                for (int i = 0; i < 4; i++)
#pragma unroll
                    for (int j = 0; j < 2; j++)
                        mma8(acc_c[i][j], af[i], bf[j]);
            }
        }
        __syncthreads();   // V, Ps free

        if (cb + 1 < 32) STAGE_V(cb + 1, mbv);
    }
#undef STAGE_KB
#undef STAGE_V
#undef SCORE_MMA

    // Ctx epilogue
    {
        float* Cg = Ctx + (size_t)b * T_ * E_ + h * DH_;
#pragma unroll
        for (int j = 0; j < 2; j++) {
            int col = wn * 16 + j * 8 + lc * 2;
#pragma unroll
            for (int i = 0; i < 4; i++) {
                int r0 = bm + wm * 64 + i * 16 + lr;
                *(float2*)(Cg + (size_t)r0 * E_ + col) =
                    make_float2(acc_c[i][j][0], acc_c[i][j][1]);
                *(float2*)(Cg + (size_t)(r0 + 8) * E_ + col) =
                    make_float2(acc_c[i][j][2], acc_c[i][j][3]);
            }
        }
    }
}

// ---------------------------------------------------------------------------
extern "C" void kernel_launch(void* const* d_in, const int* in_sizes, int n_in,
                              void* d_out, int out_size)
{
    const float* q    = (const float*)d_in[0];
    const float* k    = (const float*)d_in[1];
    const float* v    = (const float*)d_in[2];
    const int*   mask = (const int*)d_in[3];
    const float* Wq   = (const float*)d_in[4];
    const float* bq   = (const float*)d_in[5];
    const float* Wk   = (const float*)d_in[6];
    const float* bk   = (const float*)d_in[7];
    const float* Wv   = (const float*)d_in[8];
    const float* bv   = (const float*)d_in[9];
    const float* Wo   = (const float*)d_in[10];
    const float* bo   = (const float*)d_in[11];

    float* out  = (float*)d_out;
    float* attn = out + (size_t)B_ * T_ * E_;

    float *Qp, *Kp, *Vp, *Ctx;
    cudaGetSymbolAddress((void**)&Qp, g_Qp);
    cudaGetSymbolAddress((void**)&Kp, g_Kp);
    cudaGetSymbolAddress((void**)&Vp, g_Vp);
    cudaGetSymbolAddress((void**)&Ctx, g_ctx);

    cudaFuncSetAttribute(attn_fused,
                         cudaFuncAttributeMaxDynamicSharedMemorySize,
                         FZ_TOT * 4);

    dim3 gq(E_ / 128, (B_ * T_) / 128, 3);   // QKV fused: (8, 32, 3)
    GemmArgs g1;
    g1.A[0] = q;  g1.W[0] = Wq; g1.bias[0] = bq; g1.C[0] = Qp; g1.alpha[0] = SCALE_;
    g1.A[1] = k;  g1.W[1] = Wk; g1.bias[1] = bk; g1.C[1] = Kp; g1.alpha[1] = 1.0f;
    g1.A[2] = v;  g1.W[2] = Wv; g1.bias[2] = bv; g1.C[2] = Vp; g1.alpha[2] = 1.0f;
    gemm_nt_bias<<<gq, 256>>>(g1, E_, E_, E_, E_);

    attn_fused<<<dim3(T_ / 128, B_ * H_), 256, FZ_TOT * 4>>>(
        Qp, Kp, Vp, mask, attn, Ctx);

    GemmArgs g2;
    g2.A[0] = Ctx; g2.W[0] = Wo; g2.bias[0] = bo; g2.C[0] = out; g2.alpha[0] = 1.0f;
    g2.A[1] = Ctx; g2.W[1] = Wo; g2.bias[1] = bo; g2.C[1] = out; g2.alpha[1] = 1.0f;
    g2.A[2] = Ctx; g2.W[2] = Wo; g2.bias[2] = bo; g2.C[2] = out; g2.alpha[2] = 1.0f;
    gemm_nt_bias<<<dim3(E_ / 128, (B_ * T_) / 128, 1), 256>>>(g2, E_, E_, E_, E_);
}